// round 1
// baseline (speedup 1.0000x reference)
#include <cuda_runtime.h>
#include <cstddef>

#define EPS 1e-6f
#define B_   16
#define NN   1024
#define FDIM 64
#define OUTD 128
#define BM   128
#define BK   32

// Scratch for per-row scalars: D^{-1} and D^{-1/2}
__device__ float g_inv[B_ * NN];
__device__ float g_s[B_ * NN];

// ---------------------------------------------------------------------------
// Kernel 1: deg[b,i] = sum_k A[b,i,k] - A[b,i,i] + 1 ; store 1/(eps+deg),
// 1/(eps+sqrt(deg)). One warp per row.
// ---------------------------------------------------------------------------
__global__ void deg_kernel(const float* __restrict__ A) {
    int warp = (blockIdx.x * blockDim.x + threadIdx.x) >> 5;
    int lane = threadIdx.x & 31;
    if (warp >= B_ * NN) return;
    int b = warp / NN;
    int i = warp % NN;
    const float* row = A + ((size_t)b * NN + i) * NN;

    float sum = 0.f;
    const float4* r4 = (const float4*)row;
#pragma unroll
    for (int w = 0; w < 8; w++) {
        float4 v = r4[w * 32 + lane];
        sum += v.x + v.y + v.z + v.w;
    }
#pragma unroll
    for (int off = 16; off > 0; off >>= 1)
        sum += __shfl_down_sync(0xFFFFFFFFu, sum, off);
    if (lane == 0) {
        float deg = sum - row[i] + 1.0f;
        g_inv[warp] = 1.0f / (EPS + deg);
        g_s[warp]   = 1.0f / (EPS + sqrtf(deg));
    }
}

// ---------------------------------------------------------------------------
// Kernel 2: fused. Each CTA handles one batch b and 128 rows.
//   mainloop: y1 = Az@x, y3 = Az@(s*x)   (shared A reads)
//   epilogue: o1,o2,o3 built in regs -> smem chunks -> GEMM w/ kernel (smem)
// smem: [0, 8192) floats: A tile(4096) + x tile(2048) + xs tile(2048),
//       reused as ocat chunk [32][196] in epilogue.
//       [8192, 32768): kernel matrix 192x128.
// ---------------------------------------------------------------------------
__global__ __launch_bounds__(256, 1)
void fused_kernel(const float* __restrict__ x, const float* __restrict__ A,
                  const float* __restrict__ Kmat, const float* __restrict__ bias,
                  float* __restrict__ out) {
    extern __shared__ float smem[];
    float* sA  = smem;                 // [128][32]
    float* sX  = smem + 4096;          // [32][64]
    float* sXS = smem + 6144;          // [32][64]
    float* sO  = smem;                 // epilogue: [32][196] (padded stride)
    float* sK  = smem + 8192;          // [192][128]

    const int tid  = threadIdx.x;
    const int b    = blockIdx.y;
    const int row0 = blockIdx.x * BM;

    // stage kernel matrix into smem (float4)
    {
        const float4* src = (const float4*)Kmat;
        float4* dst = (float4*)sK;
#pragma unroll
        for (int i = tid; i < 192 * 128 / 4; i += 256) dst[i] = src[i];
    }

    const float* Ab = A + (size_t)b * NN * NN;
    const float* xb = x + (size_t)b * NN * FDIM;
    const float* sArr = g_s + b * NN;

    const int tr = tid >> 4;   // 0..15 -> rows tr*8..tr*8+7
    const int tc = tid & 15;   // 0..15 -> cols tc*4..tc*4+3

    float acc1[8][4];
    float acc3[8][4];
#pragma unroll
    for (int i = 0; i < 8; i++)
#pragma unroll
        for (int j = 0; j < 4; j++) { acc1[i][j] = 0.f; acc3[i][j] = 0.f; }

    for (int k0 = 0; k0 < NN; k0 += BK) {
        __syncthreads();
        // --- load A tile [128][32], zeroing the diagonal on the fly
        {
            int c4 = (tid & 7) * 4;
            int r  = tid >> 3;
#pragma unroll
            for (int rr = 0; rr < 4; rr++) {
                int row  = r + rr * 32;
                int grow = row0 + row;
                float4 v = *(const float4*)&Ab[(size_t)grow * NN + k0 + c4];
                int d = grow - k0 - c4;
                if (d == 0) v.x = 0.f;
                if (d == 1) v.y = 0.f;
                if (d == 2) v.z = 0.f;
                if (d == 3) v.w = 0.f;
                *(float4*)&sA[row * 32 + c4] = v;
            }
        }
        // --- load x tile [32][64] and s-scaled copy
        {
#pragma unroll
            for (int p = 0; p < 2; p++) {
                int i4 = tid + p * 256;        // 0..511 float4s
                int kk = i4 >> 4;
                int cc = (i4 & 15) * 4;
                float4 v = *(const float4*)&xb[(size_t)(k0 + kk) * FDIM + cc];
                *(float4*)&sX[kk * 64 + cc] = v;
                float sv = sArr[k0 + kk];
                v.x *= sv; v.y *= sv; v.z *= sv; v.w *= sv;
                *(float4*)&sXS[kk * 64 + cc] = v;
            }
        }
        __syncthreads();
#pragma unroll
        for (int kk = 0; kk < BK; kk++) {
            float a[8];
#pragma unroll
            for (int i = 0; i < 8; i++) a[i] = sA[(tr * 8 + i) * 32 + kk];
            float4 xv  = *(float4*)&sX[kk * 64 + tc * 4];
            float4 xsv = *(float4*)&sXS[kk * 64 + tc * 4];
#pragma unroll
            for (int i = 0; i < 8; i++) {
                acc1[i][0] = fmaf(a[i], xv.x,  acc1[i][0]);
                acc1[i][1] = fmaf(a[i], xv.y,  acc1[i][1]);
                acc1[i][2] = fmaf(a[i], xv.z,  acc1[i][2]);
                acc1[i][3] = fmaf(a[i], xv.w,  acc1[i][3]);
                acc3[i][0] = fmaf(a[i], xsv.x, acc3[i][0]);
                acc3[i][1] = fmaf(a[i], xsv.y, acc3[i][1]);
                acc3[i][2] = fmaf(a[i], xsv.z, acc3[i][2]);
                acc3[i][3] = fmaf(a[i], xsv.w, acc3[i][3]);
            }
        }
    }
    __syncthreads();

    // ---------------- epilogue: 4 chunks of 32 rows ----------------
    const int OSTR = 196;  // padded ocat stride (bank-conflict free)
    for (int chunk = 0; chunk < 4; chunk++) {
        if (tr >= chunk * 4 && tr < chunk * 4 + 4) {
#pragma unroll
            for (int i = 0; i < 8; i++) {
                int row  = tr * 8 + i;
                int lrow = row - chunk * 32;
                int grow = row0 + row;
                float inv = g_inv[b * NN + grow];
                float ss  = g_s[b * NN + grow];
#pragma unroll
                for (int j = 0; j < 4; j++) {
                    int f = tc * 4 + j;
                    float xval = xb[(size_t)grow * FDIM + f];
                    sO[lrow * OSTR + f]        = acc1[i][j];
                    sO[lrow * OSTR + 64 + f]   = inv * (acc1[i][j] + xval);
                    sO[lrow * OSTR + 128 + f]  = ss * (acc3[i][j] + ss * xval);
                }
            }
        }
        __syncthreads();
        // out chunk [32][128]: each thread computes 16 outputs for one row
        {
            int lrow = tid >> 3;
            int o0   = (tid & 7) * 16;
            float accO[16];
#pragma unroll
            for (int j = 0; j < 16; j++) accO[j] = 0.f;
            for (int f = 0; f < 192; f++) {
                float oc = sO[lrow * OSTR + f];
                const float4* krow = (const float4*)&sK[f * 128 + o0];
#pragma unroll
                for (int q = 0; q < 4; q++) {
                    float4 kv = krow[q];
                    accO[q * 4 + 0] = fmaf(oc, kv.x, accO[q * 4 + 0]);
                    accO[q * 4 + 1] = fmaf(oc, kv.y, accO[q * 4 + 1]);
                    accO[q * 4 + 2] = fmaf(oc, kv.z, accO[q * 4 + 2]);
                    accO[q * 4 + 3] = fmaf(oc, kv.w, accO[q * 4 + 3]);
                }
            }
            int grow = row0 + chunk * 32 + lrow;
            float* op = out + ((size_t)b * NN + grow) * OUTD + o0;
#pragma unroll
            for (int j = 0; j < 16; j += 4) {
                float4 v;
                v.x = fmaxf(accO[j + 0] + bias[o0 + j + 0], 0.f);
                v.y = fmaxf(accO[j + 1] + bias[o0 + j + 1], 0.f);
                v.z = fmaxf(accO[j + 2] + bias[o0 + j + 2], 0.f);
                v.w = fmaxf(accO[j + 3] + bias[o0 + j + 3], 0.f);
                *(float4*)&op[j] = v;
            }
        }
        __syncthreads();
    }
}

// ---------------------------------------------------------------------------
extern "C" void kernel_launch(void* const* d_in, const int* in_sizes, int n_in,
                              void* d_out, int out_size) {
    // identify inputs by element count (robust to metadata ordering)
    const float *x = nullptr, *A = nullptr, *Kmat = nullptr, *bias = nullptr;
    for (int i = 0; i < n_in; i++) {
        switch (in_sizes[i]) {
            case B_ * NN * FDIM:   x    = (const float*)d_in[i]; break;
            case B_ * NN * NN:     A    = (const float*)d_in[i]; break;
            case 3 * FDIM * OUTD:  Kmat = (const float*)d_in[i]; break;
            case OUTD:             bias = (const float*)d_in[i]; break;
        }
    }
    float* out = (float*)d_out;

    // Kernel 1: degree scalars (one warp per row)
    {
        int warps  = B_ * NN;
        int blocks = (warps * 32 + 255) / 256;
        deg_kernel<<<blocks, 256>>>(A);
    }
    // Kernel 2: fused dual-GEMM + epilogue GEMM
    {
        static int smem_set = -1;
        int smem_bytes = (8192 + 192 * 128) * sizeof(float);  // 128 KB
        if (smem_set < 0) {
            cudaFuncSetAttribute(fused_kernel,
                                 cudaFuncAttributeMaxDynamicSharedMemorySize,
                                 smem_bytes);
            smem_set = 1;
        }
        dim3 grid(NN / BM, B_);
        fused_kernel<<<grid, 256, smem_bytes>>>(x, A, Kmat, bias, out);
    }
}

// round 3
// speedup vs baseline: 5.4920x; 5.4920x over previous
#include <cuda_runtime.h>
#include <cstdint>
#include <cstddef>

#define EPS   1e-6f
#define B_    16
#define NN    1024
#define FDIM  64
#define OUTD  128
#define KC    32
#define NITER (NN / KC)

// strides (floats) chosen for conflict-free MMA fragment reads:
//   A-frag scalar reads need stride ≡ 4 (mod 32); B-frag reads need ≡ 8 (mod 32)
#define SA_STR 36
#define SB_STR 136
#define OC_STR 196
#define SK_STR 136

// smem layout (float offsets)
#define OFF_ADIAG 0
#define OFF_INV   128
#define OFF_S     256
#define OFF_DYN   384
#define OFF_A0    (OFF_DYN)
#define OFF_A1    (OFF_A0 + 128 * SA_STR)
#define OFF_B0    (OFF_A1 + 128 * SA_STR)
#define OFF_B1    (OFF_B0 + 32 * SB_STR)
#define OFF_OC    (OFF_DYN)
#define OFF_KM    (OFF_OC + 128 * OC_STR)
#define SMEM_FLOATS (OFF_KM + 192 * SK_STR)
#define SMEM_BYTES  (SMEM_FLOATS * 4)

__device__ float g_inv[B_ * NN];
__device__ float g_s[B_ * NN];

__device__ __forceinline__ float to_tf32(float v) {
    float r;
    asm("cvt.rna.tf32.f32 %0, %1;" : "=f"(r) : "f"(v));
    return r;
}
__device__ __forceinline__ void mma_tf32(float* c, const uint32_t* a, const uint32_t* b) {
    asm volatile(
        "mma.sync.aligned.m16n8k8.row.col.f32.tf32.tf32.f32 "
        "{%0,%1,%2,%3}, {%4,%5,%6,%7}, {%8,%9}, {%0,%1,%2,%3};"
        : "+f"(c[0]), "+f"(c[1]), "+f"(c[2]), "+f"(c[3])
        : "r"(a[0]), "r"(a[1]), "r"(a[2]), "r"(a[3]), "r"(b[0]), "r"(b[1]));
}

// ---------------------------------------------------------------------------
// Kernel 1: degree scalars. deg[b,i] = rowsum(A) - A[i,i] + 1
// ---------------------------------------------------------------------------
__global__ void deg_kernel(const float* __restrict__ A) {
    int warp = (blockIdx.x * blockDim.x + threadIdx.x) >> 5;
    int lane = threadIdx.x & 31;
    if (warp >= B_ * NN) return;
    const float* row = A + (size_t)warp * NN;
    float sum = 0.f;
    const float4* r4 = (const float4*)row;
#pragma unroll
    for (int w = 0; w < 8; w++) {
        float4 v = r4[w * 32 + lane];
        sum += v.x + v.y + v.z + v.w;
    }
#pragma unroll
    for (int off = 16; off > 0; off >>= 1)
        sum += __shfl_down_sync(0xFFFFFFFFu, sum, off);
    if (lane == 0) {
        float deg = sum - row[warp % NN] + 1.0f;
        g_inv[warp] = 1.0f / (EPS + deg);
        g_s[warp]   = 1.0f / (EPS + sqrtf(deg));
    }
}

// ---------------------------------------------------------------------------
// Kernel 2: fully fused. Per CTA: 128 rows of one batch.
//   GEMM1: D[128,128] = A_tile[128,1024] @ [x | s*x]   (tf32 mma.sync)
//   epilogue1: o1/o2/o3 (diagonal fixed analytically) -> ocat smem [128][192]
//   GEMM2: out = relu(ocat @ Kmat + bias)
// ---------------------------------------------------------------------------
__global__ __launch_bounds__(256, 1)
void fused_mma_kernel(const float* __restrict__ A, const float* __restrict__ x,
                      const float* __restrict__ Kmat, const float* __restrict__ bias,
                      float* __restrict__ out) {
    extern __shared__ float sm[];
    const int tid  = threadIdx.x;
    const int wid  = tid >> 5;
    const int lane = tid & 31;
    const int b    = blockIdx.y;
    const int row0 = blockIdx.x * 128;

    const int wm = wid >> 2;          // 0..1 : rows wm*64 .. +63
    const int wn = wid & 3;           // 0..3 : cols wn*32 .. +31
    const int m_base = wm * 64;
    const int n_base = wn * 32;
    const int lr = lane >> 2;         // 0..7
    const int lc = lane & 3;          // 0..3

    const float* Ab = A + (size_t)b * NN * NN;
    const float* xb = x + (size_t)b * NN * FDIM;

    // ---- stage Kmat (tf32) into smem [192][SK_STR]
    {
        const float4* src = (const float4*)Kmat;
#pragma unroll
        for (int i4 = tid; i4 < 192 * 128 / 4; i4 += 256) {
            int row = i4 >> 5, c4 = (i4 & 31) * 4;
            float4 v = src[i4];
            v.x = to_tf32(v.x); v.y = to_tf32(v.y);
            v.z = to_tf32(v.z); v.w = to_tf32(v.w);
            *(float4*)&sm[OFF_KM + row * SK_STR + c4] = v;
        }
    }
    // ---- stage per-row scalars
    if (tid < 128) {
        int grow = row0 + tid;
        sm[OFF_ADIAG + tid] = __ldg(&Ab[(size_t)grow * NN + grow]);
        sm[OFF_INV + tid]   = g_inv[b * NN + grow];
        sm[OFF_S + tid]     = g_s[b * NN + grow];
    }

    float acc[4][4][4];
#pragma unroll
    for (int mt = 0; mt < 4; mt++)
#pragma unroll
        for (int nt = 0; nt < 4; nt++)
#pragma unroll
            for (int q = 0; q < 4; q++) acc[mt][nt][q] = 0.f;

    // ---- prologue: load k-tile 0 into buf0
    float4 ra[4], rxv[2];
    float  rs[2];
    {
#pragma unroll
        for (int q = 0; q < 4; q++) {
            int e = tid + q * 256;            // 0..1023 float4s of A tile
            int r = e >> 3, c4 = (e & 7) * 4;
            ra[q] = *(const float4*)&Ab[(size_t)(row0 + r) * NN + c4];
        }
#pragma unroll
        for (int q = 0; q < 2; q++) {
            int e = tid + q * 256;            // 0..511 float4s of x tile
            int kk = e >> 4, f4 = (e & 15) * 4;
            rxv[q] = *(const float4*)&xb[(size_t)kk * FDIM + f4];
            rs[q]  = g_s[b * NN + kk];
        }
#pragma unroll
        for (int q = 0; q < 4; q++) {
            int e = tid + q * 256;
            int r = e >> 3, c4 = (e & 7) * 4;
            float4 v = ra[q];
            v.x = to_tf32(v.x); v.y = to_tf32(v.y);
            v.z = to_tf32(v.z); v.w = to_tf32(v.w);
            *(float4*)&sm[OFF_A0 + r * SA_STR + c4] = v;
        }
#pragma unroll
        for (int q = 0; q < 2; q++) {
            int e = tid + q * 256;
            int kk = e >> 4, f4 = (e & 15) * 4;
            float4 v = rxv[q], w;
            w.x = to_tf32(rs[q] * v.x); w.y = to_tf32(rs[q] * v.y);
            w.z = to_tf32(rs[q] * v.z); w.w = to_tf32(rs[q] * v.w);
            v.x = to_tf32(v.x); v.y = to_tf32(v.y);
            v.z = to_tf32(v.z); v.w = to_tf32(v.w);
            *(float4*)&sm[OFF_B0 + kk * SB_STR + f4] = v;
            *(float4*)&sm[OFF_B0 + kk * SB_STR + 64 + f4] = w;
        }
    }
    __syncthreads();

    // ---- mainloop: 32 k-tiles, double buffered, 1 sync/iter
    for (int it = 0; it < NITER; ++it) {
        const bool haveNext = (it + 1 < NITER);
        if (haveNext) {
            const int k0n = (it + 1) * KC;
#pragma unroll
            for (int q = 0; q < 4; q++) {
                int e = tid + q * 256;
                int r = e >> 3, c4 = (e & 7) * 4;
                ra[q] = *(const float4*)&Ab[(size_t)(row0 + r) * NN + k0n + c4];
            }
#pragma unroll
            for (int q = 0; q < 2; q++) {
                int e = tid + q * 256;
                int kk = e >> 4, f4 = (e & 15) * 4;
                rxv[q] = *(const float4*)&xb[(size_t)(k0n + kk) * FDIM + f4];
                rs[q]  = g_s[b * NN + k0n + kk];
            }
        }
        // compute on current buffer
        const float* sA = &sm[(it & 1) ? OFF_A1 : OFF_A0];
        const float* sB = &sm[(it & 1) ? OFF_B1 : OFF_B0];
#pragma unroll
        for (int ks = 0; ks < 4; ks++) {
            const int k = ks * 8;
            uint32_t af[4][4], bf[4][2];
#pragma unroll
            for (int mt = 0; mt < 4; mt++) {
                const float* p = sA + (m_base + mt * 16 + lr) * SA_STR + k + lc;
                af[mt][0] = __float_as_uint(p[0]);
                af[mt][1] = __float_as_uint(p[8 * SA_STR]);
                af[mt][2] = __float_as_uint(p[4]);
                af[mt][3] = __float_as_uint(p[8 * SA_STR + 4]);
            }
#pragma unroll
            for (int nt = 0; nt < 4; nt++) {
                const float* p = sB + (k + lc) * SB_STR + n_base + nt * 8 + lr;
                bf[nt][0] = __float_as_uint(p[0]);
                bf[nt][1] = __float_as_uint(p[4 * SB_STR]);
            }
#pragma unroll
            for (int mt = 0; mt < 4; mt++)
#pragma unroll
                for (int nt = 0; nt < 4; nt++)
                    mma_tf32(acc[mt][nt], af[mt], bf[nt]);
        }
        if (haveNext) {
            const int dst_a = (it & 1) ? OFF_A0 : OFF_A1;
            const int dst_b = (it & 1) ? OFF_B0 : OFF_B1;
#pragma unroll
            for (int q = 0; q < 4; q++) {
                int e = tid + q * 256;
                int r = e >> 3, c4 = (e & 7) * 4;
                float4 v = ra[q];
                v.x = to_tf32(v.x); v.y = to_tf32(v.y);
                v.z = to_tf32(v.z); v.w = to_tf32(v.w);
                *(float4*)&sm[dst_a + r * SA_STR + c4] = v;
            }
#pragma unroll
            for (int q = 0; q < 2; q++) {
                int e = tid + q * 256;
                int kk = e >> 4, f4 = (e & 15) * 4;
                float4 v = rxv[q], w;
                w.x = to_tf32(rs[q] * v.x); w.y = to_tf32(rs[q] * v.y);
                w.z = to_tf32(rs[q] * v.z); w.w = to_tf32(rs[q] * v.w);
                v.x = to_tf32(v.x); v.y = to_tf32(v.y);
                v.z = to_tf32(v.z); v.w = to_tf32(v.w);
                *(float4*)&sm[dst_b + kk * SB_STR + f4] = v;
                *(float4*)&sm[dst_b + kk * SB_STR + 64 + f4] = w;
            }
        }
        __syncthreads();
    }

    // ---- epilogue 1: fix diagonal, apply scalings, write ocat (tf32) to smem
    // cols of D: [0,64) = full-A @ x ; [64,128) = full-A @ (s*x)
#pragma unroll
    for (int mt = 0; mt < 4; mt++) {
#pragma unroll
        for (int nt = 0; nt < 4; nt++) {
            const int col = n_base + nt * 8 + lc * 2;
#pragma unroll
            for (int h = 0; h < 2; h++) {            // row halves r, r+8
                const int r = m_base + mt * 16 + lr + h * 8;
                const float ad  = sm[OFF_ADIAG + r];
                const float inv = sm[OFF_INV + r];
                const float sv  = sm[OFF_S + r];
                const float c0 = acc[mt][nt][h * 2 + 0];
                const float c1 = acc[mt][nt][h * 2 + 1];
                if (col < 64) {
                    const int f = col;
                    float2 xv = *(const float2*)&xb[(size_t)(row0 + r) * FDIM + f];
                    float o1a = c0 - ad * xv.x;
                    float o1b = c1 - ad * xv.y;
                    float o2a = inv * (o1a + xv.x);
                    float o2b = inv * (o1b + xv.y);
                    float2 w1 = make_float2(to_tf32(o1a), to_tf32(o1b));
                    float2 w2 = make_float2(to_tf32(o2a), to_tf32(o2b));
                    *(float2*)&sm[OFF_OC + r * OC_STR + f]      = w1;
                    *(float2*)&sm[OFF_OC + r * OC_STR + 64 + f] = w2;
                } else {
                    const int f = col - 64;
                    float2 xv = *(const float2*)&xb[(size_t)(row0 + r) * FDIM + f];
                    const float t = sv * sv * (1.0f - ad);
                    float o3a = sv * c0 + t * xv.x;
                    float o3b = sv * c1 + t * xv.y;
                    float2 w3 = make_float2(to_tf32(o3a), to_tf32(o3b));
                    *(float2*)&sm[OFF_OC + r * OC_STR + 128 + f] = w3;
                }
            }
        }
    }
    __syncthreads();

    // ---- GEMM2: out[128,128] = ocat[128,192] @ Kmat[192,128]
#pragma unroll
    for (int mt = 0; mt < 4; mt++)
#pragma unroll
        for (int nt = 0; nt < 4; nt++)
#pragma unroll
            for (int q = 0; q < 4; q++) acc[mt][nt][q] = 0.f;

#pragma unroll
    for (int ks = 0; ks < 24; ks++) {
        const int k = ks * 8;
        uint32_t af[4][4], bf[4][2];
#pragma unroll
        for (int mt = 0; mt < 4; mt++) {
            const float* p = &sm[OFF_OC + (m_base + mt * 16 + lr) * OC_STR + k + lc];
            af[mt][0] = __float_as_uint(p[0]);
            af[mt][1] = __float_as_uint(p[8 * OC_STR]);
            af[mt][2] = __float_as_uint(p[4]);
            af[mt][3] = __float_as_uint(p[8 * OC_STR + 4]);
        }
#pragma unroll
        for (int nt = 0; nt < 4; nt++) {
            const float* p = &sm[OFF_KM + (k + lc) * SK_STR + n_base + nt * 8 + lr];
            bf[nt][0] = __float_as_uint(p[0]);
            bf[nt][1] = __float_as_uint(p[4 * SK_STR]);
        }
#pragma unroll
        for (int mt = 0; mt < 4; mt++)
#pragma unroll
            for (int nt = 0; nt < 4; nt++)
                mma_tf32(acc[mt][nt], af[mt], bf[nt]);
    }

    // ---- bias + relu + store
#pragma unroll
    for (int mt = 0; mt < 4; mt++) {
#pragma unroll
        for (int nt = 0; nt < 4; nt++) {
            const int col = n_base + nt * 8 + lc * 2;
            float2 bv = *(const float2*)&bias[col];
#pragma unroll
            for (int h = 0; h < 2; h++) {
                const int r = m_base + mt * 16 + lr + h * 8;
                float2 o;
                o.x = fmaxf(acc[mt][nt][h * 2 + 0] + bv.x, 0.f);
                o.y = fmaxf(acc[mt][nt][h * 2 + 1] + bv.y, 0.f);
                *(float2*)&out[((size_t)b * NN + row0 + r) * OUTD + col] = o;
            }
        }
    }
}

// ---------------------------------------------------------------------------
extern "C" void kernel_launch(void* const* d_in, const int* in_sizes, int n_in,
                              void* d_out, int out_size) {
    const float *x = nullptr, *A = nullptr, *Kmat = nullptr, *bias = nullptr;
    for (int i = 0; i < n_in; i++) {
        switch (in_sizes[i]) {
            case B_ * NN * FDIM:  x    = (const float*)d_in[i]; break;
            case B_ * NN * NN:    A    = (const float*)d_in[i]; break;
            case 3 * FDIM * OUTD: Kmat = (const float*)d_in[i]; break;
            case OUTD:            bias = (const float*)d_in[i]; break;
        }
    }
    float* out = (float*)d_out;

    static bool attr_set = false;
    if (!attr_set) {
        cudaFuncSetAttribute(fused_mma_kernel,
                             cudaFuncAttributeMaxDynamicSharedMemorySize, SMEM_BYTES);
        attr_set = true;
    }

    deg_kernel<<<(B_ * NN * 32 + 255) / 256, 256>>>(A);
    fused_mma_kernel<<<dim3(NN / 128, B_), 256, SMEM_BYTES>>>(A, x, Kmat, bias, out);
}